// round 10
// baseline (speedup 1.0000x reference)
#include <cuda_runtime.h>
#include <cuda_bf16.h>
#include <math.h>
#include <stdint.h>

#define NB 32
#define NL 512
#define NHID 512
#define NH 8
#define NE 64
#define NTOPK 62
#define FLEFT 102
#define PI_D 3.14159265358979323846

typedef __nv_bfloat16 bf16;

// ---------------- static device scratch ----------------
__device__ float d_g[NL];
__device__ bf16 d_We[1536 * 1536];                 // [Wq;Wk;Wv] expanded (B-pattern, 3-term)
__device__ bf16 d_Wde[512 * 1536];                 // Wd expanded (B-pattern)
__device__ bf16 d_xe[16384 * 1536];                // x expanded (A-pattern)
__device__ bf16 d_Ge[512 * 1536];                  // G expanded (A-pattern)
__device__ bf16 d_xte[(size_t)NB * 512 * 1536];    // x^T expanded (B-pattern), per batch
__device__ bf16 d_Xge[16384 * 1536];               // filtered X expanded (A-pattern, via expA)
__device__ float d_QKVf[(size_t)16384 * 1536];     // Qf|Kf|Vf (f32)
__device__ float d_V[(size_t)16384 * 512];         // unfiltered V (time branch)
__device__ bf16 d_Qfe[(size_t)NB * NH * NL * 192];
__device__ bf16 d_Kfe[(size_t)NB * NH * NL * 192];
__device__ bf16 d_Vfte[(size_t)NB * NH * NE * 1024]; // V^T 2-term (hi,hi)
__device__ bf16 d_S[(size_t)NB * NH * NL * NL];    // raw scores, bf16
__device__ bf16 d_Se[(size_t)NB * NH * NL * 1024]; // probs 2-term (hi,lo)
__device__ float d_ctx[(size_t)16384 * 512];       // time-branch context
__device__ bf16 d_ctxe[(size_t)16384 * 1536];      // ctx expanded (A-pattern, via expA)
__device__ float d_Hb[(size_t)16384 * 512];
__device__ float d_mvp[(size_t)NB * NH * 16 * NL]; // per-CTA diag partials
__device__ int d_delay[NB * NTOPK];
__device__ float d_w[NB * NTOPK];

// ---------------- helpers ----------------
__device__ __forceinline__ uint32_t smem_u32(const void* p) {
    uint32_t r;
    asm("{ .reg .u64 t; cvta.to.shared.u64 t, %1; cvt.u32.u64 %0, t; }" : "=r"(r) : "l"(p));
    return r;
}
__device__ __forceinline__ void cpa16(uint32_t s, const void* g) {
    asm volatile("cp.async.cg.shared.global [%0], [%1], 16;\n" :: "r"(s), "l"(g));
}
__device__ __forceinline__ void ldm_x4(uint32_t& r0, uint32_t& r1, uint32_t& r2, uint32_t& r3,
                                       uint32_t a) {
    asm volatile("ldmatrix.sync.aligned.m8n8.x4.shared.b16 {%0,%1,%2,%3}, [%4];\n"
                 : "=r"(r0), "=r"(r1), "=r"(r2), "=r"(r3) : "r"(a));
}
__device__ __forceinline__ void mma16816(float* c, const uint32_t* a, const uint32_t* b) {
    asm volatile(
        "mma.sync.aligned.m16n8k16.row.col.f32.bf16.bf16.f32 "
        "{%0,%1,%2,%3},{%4,%5,%6,%7},{%8,%9},{%0,%1,%2,%3};\n"
        : "+f"(c[0]), "+f"(c[1]), "+f"(c[2]), "+f"(c[3])
        : "r"(a[0]), "r"(a[1]), "r"(a[2]), "r"(a[3]), "r"(b[0]), "r"(b[1]));
}
__device__ __forceinline__ unsigned short bfbits(bf16 h) {
    return __bfloat16_as_ushort(h);
}

// ---------------- bf16 HMMA NT GEMM, 3-stage cp.async pipeline ----------------
// C = alpha*A·B^T (+beta*C)(+bias)(+resid); optional expA (3-term A-pattern output),
// optional bf16 C (c_bf16), optional per-CTA diagonal partial sums (diag).
template <int BN>
__global__ void __launch_bounds__(256, 2) bgemm(
    const bf16* __restrict__ Ag, const bf16* __restrict__ Bg, float* __restrict__ Cg,
    int lda, int ldb, int ldc, int Kx,
    long long oAb, long long oAh, long long oBb, long long oBh,
    long long oCb, long long oCh, int Hd,
    const float* __restrict__ bias, const float* __restrict__ resid,
    bf16* __restrict__ expAg, float* __restrict__ diag, int c_bf16,
    float alpha, float beta)
{
    constexpr int BM = 128, LT = 72;
    constexpr int ASTG = BM * LT * 2;
    constexpr int BSTG = BN * LT * 2;
    constexpr int STG = ASTG + BSTG;
    constexpr int NT = BN / 16;
    const int NC = Kx >> 6;

    extern __shared__ bf16 sm[];
    const uint32_t sbase = smem_u32(sm);

    const int tid = threadIdx.x;
    const int lane = tid & 31, warp = tid >> 5;
    const int wm = warp >> 1, wn = warp & 1;

    const int z = blockIdx.z, zb = z / Hd, zh = z % Hd;
    const int row0 = blockIdx.y * BM, col0 = blockIdx.x * BN;
    const int lda2 = lda * 2, ldb2 = ldb * 2;
    const char* A = (const char*)(Ag + zb * oAb + zh * oAh) + (size_t)row0 * lda2;
    const char* B = (const char*)(Bg + zb * oBb + zh * oBh) + (size_t)col0 * ldb2;
    float* C = (!c_bf16 && Cg) ? (Cg + zb * oCb + zh * oCh) : (float*)0;
    bf16* Cb = (c_bf16 && Cg) ? ((bf16*)Cg + zb * oCb + zh * oCh) : (bf16*)0;
    const float* R = resid ? (resid + zb * oCb + zh * oCh) : (const float*)0;
    bf16* EA = expAg ? (expAg + (size_t)zb * oCb * 3 + (size_t)zh * oCh * 3) : (bf16*)0;
    const int lde = ldc * 3;

    float acc[2][NT][4];
#pragma unroll
    for (int i = 0; i < 2; i++)
#pragma unroll
        for (int j = 0; j < NT; j++)
#pragma unroll
            for (int k = 0; k < 4; k++) acc[i][j][k] = 0.f;

    auto load_stage = [&](int c) {
        int s = c % 3;
        uint32_t sa = sbase + s * STG;
        const char* Ac = A + c * 128;
#pragma unroll
        for (int i = 0; i < (BM * 8) / 256; i++) {
            int cc = tid + i * 256, r = cc >> 3, sg = (cc & 7) * 16;
            cpa16(sa + r * (LT * 2) + sg, Ac + (size_t)r * lda2 + sg);
        }
        uint32_t sb = sa + ASTG;
        const char* Bc = B + c * 128;
#pragma unroll
        for (int i = 0; i < (BN * 8) / 256; i++) {
            int cc = tid + i * 256, r = cc >> 3, sg = (cc & 7) * 16;
            cpa16(sb + r * (LT * 2) + sg, Bc + (size_t)r * ldb2 + sg);
        }
        asm volatile("cp.async.commit_group;\n");
    };

    load_stage(0);
    load_stage(1);

    const int g = lane >> 3, ri = lane & 7;
    for (int c = 0; c < NC; c++) {
        if (c < NC - 1) {
            asm volatile("cp.async.wait_group 1;\n");
        } else {
            asm volatile("cp.async.wait_group 0;\n");
        }
        __syncthreads();
        if (c + 2 < NC) load_stage(c + 2);

        int s = c % 3;
        uint32_t sa = sbase + s * STG;
        uint32_t sb = sa + ASTG;
#pragma unroll
        for (int k16 = 0; k16 < 4; k16++) {
            uint32_t a[2][4];
#pragma unroll
            for (int mt = 0; mt < 2; mt++) {
                int row = wm * 32 + mt * 16 + ri + (g & 1) * 8;
                ldm_x4(a[mt][0], a[mt][1], a[mt][2], a[mt][3],
                       sa + row * (LT * 2) + k16 * 32 + (g >> 1) * 16);
            }
            uint32_t b[NT][2];
#pragma unroll
            for (int np = 0; np < NT / 2; np++) {
                int nrow = wn * (BN / 2) + np * 16 + ri + (g >> 1) * 8;
                ldm_x4(b[2 * np][0], b[2 * np][1], b[2 * np + 1][0], b[2 * np + 1][1],
                       sb + nrow * (LT * 2) + k16 * 32 + (g & 1) * 16);
            }
#pragma unroll
            for (int mt = 0; mt < 2; mt++)
#pragma unroll
                for (int nt = 0; nt < NT; nt++)
                    mma16816(acc[mt][nt], a[mt], b[nt]);
        }
    }
    __syncthreads();

    // epilogue
    float* bins = (float*)sm;  // mainloop smem is dead now
    if (diag) {
        for (int i = tid; i < 512; i += 256) bins[i] = 0.f;
        __syncthreads();
    }
    const int gq = lane >> 2, tq = lane & 3;
#pragma unroll
    for (int mt = 0; mt < 2; mt++) {
#pragma unroll
        for (int nt = 0; nt < NT; nt++) {
            int ccol = col0 + wn * (BN / 2) + nt * 8 + tq * 2;
#pragma unroll
            for (int h = 0; h < 2; h++) {
                int r = row0 + wm * 32 + mt * 16 + gq + h * 8;
                size_t off = (size_t)r * ldc + ccol;
                float v0 = alpha * acc[mt][nt][2 * h];
                float v1 = alpha * acc[mt][nt][2 * h + 1];
                if (beta != 0.f && C) {
                    float2 p = *(const float2*)&C[off];
                    v0 += beta * p.x; v1 += beta * p.y;
                }
                if (bias) { v0 += bias[ccol]; v1 += bias[ccol + 1]; }
                if (R) {
                    float2 p = *(const float2*)&R[off];
                    v0 += p.x; v1 += p.y;
                }
                if (C) {
                    float2 o; o.x = v0; o.y = v1;
                    *(float2*)&C[off] = o;
                }
                if (Cb) {
                    uint32_t pk = (uint32_t)bfbits(__float2bfloat16(v0)) |
                                  ((uint32_t)bfbits(__float2bfloat16(v1)) << 16);
                    *(uint32_t*)&Cb[off] = pk;
                }
                if (diag) {
                    atomicAdd(&bins[(r - ccol) & 511], v0);
                    atomicAdd(&bins[(r - ccol - 1) & 511], v1);
                }
                if (EA) {
                    bf16 h0 = __float2bfloat16(v0);
                    bf16 l0 = __float2bfloat16(v0 - __bfloat162float(h0));
                    bf16 h1 = __float2bfloat16(v1);
                    bf16 l1 = __float2bfloat16(v1 - __bfloat162float(h1));
                    uint32_t u0 = (uint32_t)bfbits(h0) | ((uint32_t)bfbits(l0) << 16);
                    uint32_t u1 = (uint32_t)bfbits(h0) | ((uint32_t)bfbits(h1) << 16);
                    uint32_t u2 = (uint32_t)bfbits(l1) | ((uint32_t)bfbits(h1) << 16);
                    uint32_t* q = (uint32_t*)(EA + (size_t)r * lde + 3 * ccol);
                    q[0] = u0; q[1] = u1; q[2] = u2;
                }
            }
        }
    }
    if (diag) {
        __syncthreads();
        int slot = z * (gridDim.x * gridDim.y) + blockIdx.y * gridDim.x + blockIdx.x;
        float* dd = diag + (size_t)slot * 512;
        for (int i = tid; i < 512; i += 256) dd[i] = bins[i];
    }
}

// ---------------- setup + expansions ----------------
__global__ void setup_misc() {
    int t = threadIdx.x;
    double s = 0.0;
    for (int f = FLEFT; f < 256; ++f)
        s += 2.0 * cos(2.0 * PI_D * (double)f * (double)t / 512.0);
    s += (t & 1) ? -1.0 : 1.0;
    d_g[t] = (float)(s / 512.0);
}
__global__ void expand_G() {
    int l = blockIdx.x, m = threadIdx.x;
    float v = d_g[(l - m) & (NL - 1)];
    bf16 h = __float2bfloat16(v);
    bf16 lo = __float2bfloat16(v - __bfloat162float(h));
    bf16* d = d_Ge + (size_t)l * 1536 + 3 * m;
    d[0] = h; d[1] = lo; d[2] = h;
}
// PAT 0 = A-pattern (hi,lo,hi); PAT 1 = B-pattern (hi,hi,lo)
template <int PAT>
__global__ void expand_k(const float* __restrict__ src, bf16* __restrict__ dst,
                         int K, int src_ld, int Hd, long long oZb, long long oZh, long long dstZ) {
    int z = blockIdx.z, zb = z / Hd, zh = z % Hd;
    const float* s = src + zb * oZb + zh * oZh + (size_t)blockIdx.y * src_ld;
    bf16* d = dst + (size_t)z * dstZ + (size_t)blockIdx.y * (3 * K);
    for (int k = blockIdx.x * blockDim.x + threadIdx.x; k < K; k += gridDim.x * blockDim.x) {
        float v = s[k];
        bf16 h = __float2bfloat16(v);
        bf16 lo = __float2bfloat16(v - __bfloat162float(h));
        if (PAT == 0) { d[3*k] = h; d[3*k+1] = lo; d[3*k+2] = h; }
        else          { d[3*k] = h; d[3*k+1] = h;  d[3*k+2] = lo; }
    }
}
// transpose + B-pattern (TERMS=3: hi,hi,lo; TERMS=2: hi,hi): src [Krows,Ncols] -> dst [Ncols,TERMS*Krows]
template <int TERMS>
__global__ void texpand_b(const float* __restrict__ src, bf16* __restrict__ dst,
                          int src_ld, int Krows, int Ncols, int Hd,
                          long long oZb, long long oZh, long long dstZ) {
    __shared__ float t[32][33];
    int z = blockIdx.z, zb = z / Hd, zh = z % Hd;
    const float* s = src + zb * oZb + zh * oZh;
    bf16* d = dst + (size_t)z * dstZ;
    int k0 = blockIdx.x * 32, n0 = blockIdx.y * 32;
    int tx = threadIdx.x, ty = threadIdx.y;
#pragma unroll
    for (int i = 0; i < 32; i += 8)
        t[ty + i][tx] = s[(size_t)(k0 + ty + i) * src_ld + n0 + tx];
    __syncthreads();
#pragma unroll
    for (int i = 0; i < 32; i += 8) {
        int n = n0 + ty + i, k = k0 + tx;
        float v = t[tx][ty + i];
        bf16 h = __float2bfloat16(v);
        bf16* dd = d + (size_t)n * (TERMS * Krows) + TERMS * k;
        dd[0] = h; dd[1] = h;
        if (TERMS == 3) dd[2] = __float2bfloat16(v - __bfloat162float(h));
    }
}

// ---------------- top-k over per-CTA diag partials ----------------
__global__ void topk_kernel() {
    int b = blockIdx.x, t = threadIdx.x;
    __shared__ float mv[NL], rv[256], selw[NTOPK];
    __shared__ int ri[256], seld[NTOPK];
    for (int d = t; d < NL; d += 256) {
        float s = 0.f;
        for (int sl = 0; sl < 128; sl++) s += d_mvp[((size_t)b * 128 + sl) * 512 + d];
        mv[d] = s * (1.f / 64.f);  // corr = 8*S, mean over 512 channels
    }
    __syncthreads();
    for (int k = 0; k < NTOPK; k++) {
        float best = -1e30f; int bi = NL;
        for (int d = t; d < NL; d += 256) {
            float x = mv[d];
            if (x > best || (x == best && d < bi)) { best = x; bi = d; }
        }
        rv[t] = best; ri[t] = bi;
        __syncthreads();
        for (int off = 128; off; off >>= 1) {
            if (t < off && (rv[t+off] > rv[t] || (rv[t+off] == rv[t] && ri[t+off] < ri[t]))) {
                rv[t] = rv[t+off]; ri[t] = ri[t+off];
            }
            __syncthreads();
        }
        if (t == 0) { selw[k] = rv[0]; seld[k] = ri[0]; mv[ri[0]] = -1e30f; }
        __syncthreads();
    }
    if (t == 0) {
        float m = selw[0], s = 0.f;
        for (int k = 0; k < NTOPK; k++) { float e = expf(selw[k] - m); selw[k] = e; s += e; }
        float inv = 1.f / s;
        for (int k = 0; k < NTOPK; k++) {
            d_w[b * NTOPK + k] = selw[k] * inv;
            d_delay[b * NTOPK + k] = seld[k];
        }
    }
}

__global__ void delay_agg(const float* __restrict__ V, float* __restrict__ ctx) {
    int l = blockIdx.x, b = blockIdx.y, t = threadIdx.x;
    __shared__ float w[NTOPK];
    __shared__ int dl[NTOPK];
    if (t < NTOPK) { w[t] = d_w[b * NTOPK + t]; dl[t] = d_delay[b * NTOPK + t]; }
    __syncthreads();
    const float* Vb = V + (size_t)b * NL * NHID + t;
    float acc = 0.f;
#pragma unroll 2
    for (int k = 0; k < NTOPK; k++)
        acc += w[k] * Vb[(size_t)((l + dl[k]) & (NL - 1)) * NHID];
    ctx[(size_t)b * NL * NHID + (size_t)l * NHID + t] = 0.5f * acc;
}

// softmax(+mask) over bf16 scores, emitting 2-term (hi,lo) expanded probs
__global__ void softmax_se(const bf16* __restrict__ S, const float* __restrict__ mask,
                           bf16* __restrict__ Se) {
    size_t row = blockIdx.x;
    int b = (int)(row / (NH * NL)), i = (int)(row % NL);
    const bf16* s = S + row * NL;
    const float* mr = mask + (size_t)b * NL * NL + (size_t)i * NL;
    bf16* se = Se + row * 1024;
    int t = threadIdx.x;
    float v[4], mx = -1e30f;
#pragma unroll
    for (int k = 0; k < 4; k++) {
        v[k] = __bfloat162float(s[t + 128*k]) + mr[t + 128*k];
        mx = fmaxf(mx, v[k]);
    }
    __shared__ float red[32];
#pragma unroll
    for (int o = 16; o; o >>= 1) mx = fmaxf(mx, __shfl_xor_sync(~0u, mx, o));
    if ((t & 31) == 0) red[t >> 5] = mx;
    __syncthreads();
    mx = fmaxf(fmaxf(red[0], red[1]), fmaxf(red[2], red[3]));
    float sum = 0.f;
#pragma unroll
    for (int k = 0; k < 4; k++) { v[k] = expf(v[k] - mx); sum += v[k]; }
#pragma unroll
    for (int o = 16; o; o >>= 1) sum += __shfl_xor_sync(~0u, sum, o);
    __syncthreads();
    if ((t & 31) == 0) red[t >> 5] = sum;
    __syncthreads();
    float inv = 1.f / (red[0] + red[1] + red[2] + red[3]);
#pragma unroll
    for (int k = 0; k < 4; k++) {
        float p = v[k] * inv;
        int col = t + 128 * k;
        bf16 h = __float2bfloat16(p);
        bf16 lo = __float2bfloat16(p - __bfloat162float(h));
        uint32_t pk = (uint32_t)bfbits(h) | ((uint32_t)bfbits(lo) << 16);
        *(uint32_t*)&se[2 * col] = pk;
    }
}

__global__ void layernorm(const float* __restrict__ Hb, const float* __restrict__ w,
                          const float* __restrict__ bz, float* __restrict__ out) {
    size_t row = blockIdx.x;
    const float* h = Hb + row * NHID;
    float* o = out + row * NHID;
    int t = threadIdx.x;
    float v[4], s = 0.f;
#pragma unroll
    for (int k = 0; k < 4; k++) { v[k] = h[t + 128*k]; s += v[k]; }
    __shared__ float red[32];
#pragma unroll
    for (int o2 = 16; o2; o2 >>= 1) s += __shfl_xor_sync(~0u, s, o2);
    if ((t & 31) == 0) red[t >> 5] = s;
    __syncthreads();
    float mu = (red[0] + red[1] + red[2] + red[3]) / (float)NHID;
    float s2 = 0.f;
#pragma unroll
    for (int k = 0; k < 4; k++) { float d = v[k] - mu; s2 += d * d; }
#pragma unroll
    for (int o2 = 16; o2; o2 >>= 1) s2 += __shfl_xor_sync(~0u, s2, o2);
    __syncthreads();
    if ((t & 31) == 0) red[t >> 5] = s2;
    __syncthreads();
    float inv = rsqrtf((red[0] + red[1] + red[2] + red[3]) / (float)NHID + 1e-12f);
#pragma unroll
    for (int k = 0; k < 4; k++) {
        int c = t + 128*k;
        o[c] = w[c] * ((v[k] - mu) * inv) + bz[c];
    }
}

// ---------------- launch ----------------
extern "C" void kernel_launch(void* const* d_in, const int* in_sizes, int n_in,
                              void* d_out, int out_size) {
    (void)in_sizes; (void)n_in; (void)out_size;
    const float* x = (const float*)d_in[0];
    const float* mask = (const float*)d_in[1];
    const float* Wq = (const float*)d_in[2];
    const float* Wk = (const float*)d_in[4];
    const float* Wv = (const float*)d_in[6];
    const float* bv = (const float*)d_in[7];
    const float* Wd = (const float*)d_in[8];
    const float* bd = (const float*)d_in[9];
    const float* lnw = (const float*)d_in[10];
    const float* lnb = (const float*)d_in[11];
    float* out = (float*)d_out;

    bf16 *pWe, *pWde, *pxe, *pGe, *pxte, *pXge, *pQfe, *pKfe, *pVfte, *pSb, *pSe, *pctxe;
    float *pQKVf, *pV, *pctx, *pHb, *pmvp;
    cudaGetSymbolAddress((void**)&pWe, d_We);
    cudaGetSymbolAddress((void**)&pWde, d_Wde);
    cudaGetSymbolAddress((void**)&pxe, d_xe);
    cudaGetSymbolAddress((void**)&pGe, d_Ge);
    cudaGetSymbolAddress((void**)&pxte, d_xte);
    cudaGetSymbolAddress((void**)&pXge, d_Xge);
    cudaGetSymbolAddress((void**)&pQfe, d_Qfe);
    cudaGetSymbolAddress((void**)&pKfe, d_Kfe);
    cudaGetSymbolAddress((void**)&pVfte, d_Vfte);
    cudaGetSymbolAddress((void**)&pSb, d_S);
    cudaGetSymbolAddress((void**)&pSe, d_Se);
    cudaGetSymbolAddress((void**)&pctxe, d_ctxe);
    cudaGetSymbolAddress((void**)&pQKVf, d_QKVf);
    cudaGetSymbolAddress((void**)&pV, d_V);
    cudaGetSymbolAddress((void**)&pctx, d_ctx);
    cudaGetSymbolAddress((void**)&pHb, d_Hb);
    cudaGetSymbolAddress((void**)&pmvp, d_mvp);

    const int SM128 = 3 * (128 + 128) * 72 * 2;  // 110592 B (3 stages)
    const int SM64  = 3 * (128 + 64) * 72 * 2;   // 82944 B
    cudaFuncSetAttribute(bgemm<128>, cudaFuncAttributeMaxDynamicSharedMemorySize, SM128);
    cudaFuncSetAttribute(bgemm<64>,  cudaFuncAttributeMaxDynamicSharedMemorySize, SM64);

    const long long L1536 = 1536LL * 512;
    const long long BLH = 512LL * 512;
    const long long BLL = 512LL * 512;

    setup_misc<<<1, 512>>>();
    expand_G<<<512, 512>>>();
    expand_k<1><<<dim3(2,512,1), 256>>>(Wq, pWe,             512, 512, 1, 0, 0, 0);
    expand_k<1><<<dim3(2,512,1), 256>>>(Wk, pWe + 512*1536,  512, 512, 1, 0, 0, 0);
    expand_k<1><<<dim3(2,512,1), 256>>>(Wv, pWe + 1024*1536, 512, 512, 1, 0, 0, 0);
    expand_k<1><<<dim3(2,512,1), 256>>>(Wd, pWde,            512, 512, 1, 0, 0, 0);
    expand_k<0><<<dim3(2,16384,1), 256>>>(x, pxe,            512, 512, 1, 0, 0, 0);
    // x^T expanded per batch (B operand of the filter GEMM)
    texpand_b<3><<<dim3(16,16,32), dim3(32,8)>>>(x, pxte, 512, 512, 512, 1,
        BLH, 0, 512LL*1536);

    // 1) filter X: Xge = expand(G @ x[b])  (C store skipped; only expA emitted)
    bgemm<128><<<dim3(4,4,32), 256, SM128>>>(pGe, pxte, nullptr,
        1536, 1536, 512, 1536, 0,0, 512LL*1536,0, BLH,0, 1,
        nullptr, nullptr, pXge, nullptr, 0, 1.f, 0.f);

    // 2) filtered projections: QKVf = Xg @ [Wq;Wk;Wv]^T  (band kills bias exactly)
    bgemm<128><<<dim3(12,128,1), 256, SM128>>>(pXge, pWe, pQKVf,
        1536, 1536, 1536, 1536, 0,0, 0,0, 0,0, 1,
        nullptr, nullptr, nullptr, nullptr, 0, 1.f, 0.f);

    // 3) unfiltered V (time branch): V = x @ Wv^T + bv
    bgemm<128><<<dim3(4,128,1), 256, SM128>>>(pxe, pWe + 1024*1536, pV,
        1536, 1536, 512, 1536, 0,0, 0,0, 0,0, 1,
        bv, nullptr, nullptr, nullptr, 0, 1.f, 0.f);

    // per-head expansions from QKVf
    expand_k<0><<<dim3(1,512,256), 64>>>(pQKVf, pQfe, 64, 1536, 8, L1536, 64, 512LL*192);
    expand_k<1><<<dim3(1,512,256), 64>>>(pQKVf + 512, pKfe, 64, 1536, 8, L1536, 64, 512LL*192);
    texpand_b<2><<<dim3(16,2,256), dim3(32,8)>>>(pQKVf + 1024, pVfte, 1536, 512, 64, 8,
        L1536, 64, 64LL*1024);

    // 4) scores: S(bf16) = 0.125 * Qf_h @ Kf_h^T, with fused per-CTA diag partials
    bgemm<128><<<dim3(4,4,256), 256, SM128>>>(pQfe, pKfe, (float*)pSb,
        192, 192, 512, 192, 8*512LL*192, 512LL*192, 8*512LL*192, 512LL*192,
        8*BLL, BLL, 8, nullptr, nullptr, nullptr, pmvp, 1, 0.125f, 0.f);

    // top-k over summed diag partials
    topk_kernel<<<NB, 256>>>();

    // time branch gather
    delay_agg<<<dim3(NL, NB), NHID>>>(pV, pctx);

    // softmax (+mask) -> 2-term expanded probs Se
    softmax_se<<<NB * NH * NL, 128>>>(pSb, mask, pSe);

    // 5) ctxe = expand(0.5*probs@Vf_h + ctx_time)  (resid carries time branch; no C store)
    bgemm<64><<<dim3(1,4,256), 256, SM64>>>(pSe, pVfte, nullptr,
        1024, 1024, 512, 1024, 8*512LL*1024, 512LL*1024, 8*64LL*1024, 64LL*1024,
        BLH, 64, 8, nullptr, pctx, pctxe, nullptr, 0, 0.5f, 0.f);

    // 6) output projection + bias + residual
    bgemm<128><<<dim3(4,128,1), 256, SM128>>>(pctxe, pWde, pHb,
        1536, 1536, 512, 1536, 0,0, 0,0, 0,0, 1,
        bd, x, nullptr, nullptr, 0, 1.f, 0.f);

    layernorm<<<NB * NL, 128>>>(pHb, lnw, lnb, out);
}

// round 12
// speedup vs baseline: 1.1754x; 1.1754x over previous
#include <cuda_runtime.h>
#include <cuda_fp16.h>
#include <math.h>
#include <stdint.h>

#define NB 32
#define NL 512
#define NHID 512
#define NH 8
#define NE 64
#define NTOPK 62
#define FLEFT 102
#define PI_D 3.14159265358979323846

typedef __half h16;

// ---------------- static device scratch ----------------
__device__ float d_g[NL];
__device__ h16 d_We[1536 * 1024];                  // [Wq;Wk;Wv] expanded (B-pattern hi,hi)
__device__ h16 d_Wde[512 * 1024];                  // Wd expanded (B-pattern)
__device__ h16 d_xe[16384 * 1024];                 // x expanded (A-pattern hi,lo)
__device__ h16 d_Ge[512 * 1024];                   // G expanded (A-pattern)
__device__ h16 d_xte[(size_t)NB * 512 * 1024];     // x^T expanded (B-pattern), per batch
__device__ h16 d_Xge[16384 * 1024];                // filtered X expanded (A-pattern, via expA)
__device__ float d_QKVf[(size_t)16384 * 1536];     // Qf|Kf|Vf (f32)
__device__ float d_V[(size_t)16384 * 512];         // unfiltered V (time branch)
__device__ h16 d_Qfe[(size_t)NB * NH * NL * 128];  // per-head Q (A-pattern)
__device__ h16 d_Kfe[(size_t)NB * NH * NL * 128];  // per-head K (B-pattern)
__device__ h16 d_Vfte[(size_t)NB * NH * NE * 1024];// V^T 2-term (hi,hi)
__device__ h16 d_S[(size_t)NB * NH * NL * NL];     // raw scores, fp16
__device__ h16 d_Se[(size_t)NB * NH * NL * 1024];  // probs 2-term (hi,lo)
__device__ float d_ctx[(size_t)16384 * 512];       // time-branch context
__device__ h16 d_ctxe[(size_t)16384 * 1024];       // ctx expanded (A-pattern, via expA)
__device__ float d_Hb[(size_t)16384 * 512];
__device__ float d_mvp[(size_t)NB * NH * 16 * NL]; // per-CTA diag partials
__device__ int d_delay[NB * NTOPK];
__device__ float d_w[NB * NTOPK];

// ---------------- helpers ----------------
__device__ __forceinline__ uint32_t smem_u32(const void* p) {
    uint32_t r;
    asm("{ .reg .u64 t; cvta.to.shared.u64 t, %1; cvt.u32.u64 %0, t; }" : "=r"(r) : "l"(p));
    return r;
}
__device__ __forceinline__ void cpa16(uint32_t s, const void* g) {
    asm volatile("cp.async.cg.shared.global [%0], [%1], 16;\n" :: "r"(s), "l"(g));
}
__device__ __forceinline__ void ldm_x4(uint32_t& r0, uint32_t& r1, uint32_t& r2, uint32_t& r3,
                                       uint32_t a) {
    asm volatile("ldmatrix.sync.aligned.m8n8.x4.shared.b16 {%0,%1,%2,%3}, [%4];\n"
                 : "=r"(r0), "=r"(r1), "=r"(r2), "=r"(r3) : "r"(a));
}
__device__ __forceinline__ void mma16816(float* c, const uint32_t* a, const uint32_t* b) {
    asm volatile(
        "mma.sync.aligned.m16n8k16.row.col.f32.f16.f16.f32 "
        "{%0,%1,%2,%3},{%4,%5,%6,%7},{%8,%9},{%0,%1,%2,%3};\n"
        : "+f"(c[0]), "+f"(c[1]), "+f"(c[2]), "+f"(c[3])
        : "r"(a[0]), "r"(a[1]), "r"(a[2]), "r"(a[3]), "r"(b[0]), "r"(b[1]));
}
__device__ __forceinline__ unsigned short hbits(h16 h) {
    return __half_as_ushort(h);
}
__device__ __forceinline__ uint32_t pack_hilo(float v) {
    h16 h = __float2half(v);
    h16 lo = __float2half(v - __half2float(h));
    return (uint32_t)hbits(h) | ((uint32_t)hbits(lo) << 16);
}

// ---------------- fp16 HMMA NT GEMM, 3-stage cp.async pipeline ----------------
// C = alpha*A·B^T (+bias)(+resid); optional expA (2-term hi,lo A-pattern output),
// optional fp16 C (c_h16), optional per-CTA diagonal partial sums (diag).
template <int BN>
__global__ void __launch_bounds__(256, 2) bgemm(
    const h16* __restrict__ Ag, const h16* __restrict__ Bg, float* __restrict__ Cg,
    int lda, int ldb, int ldc, int Kx,
    long long oAb, long long oAh, long long oBb, long long oBh,
    long long oCb, long long oCh, int Hd,
    const float* __restrict__ bias, const float* __restrict__ resid,
    h16* __restrict__ expAg, float* __restrict__ diag, int c_h16,
    float alpha)
{
    constexpr int BM = 128, LT = 72;
    constexpr int ASTG = BM * LT * 2;
    constexpr int BSTG = BN * LT * 2;
    constexpr int STG = ASTG + BSTG;
    constexpr int NT = BN / 16;
    const int NC = Kx >> 6;

    extern __shared__ h16 sm[];
    const uint32_t sbase = smem_u32(sm);

    const int tid = threadIdx.x;
    const int lane = tid & 31, warp = tid >> 5;
    const int wm = warp >> 1, wn = warp & 1;

    const int z = blockIdx.z, zb = z / Hd, zh = z % Hd;
    const int row0 = blockIdx.y * BM, col0 = blockIdx.x * BN;
    const int lda2 = lda * 2, ldb2 = ldb * 2;
    const char* A = (const char*)(Ag + zb * oAb + zh * oAh) + (size_t)row0 * lda2;
    const char* B = (const char*)(Bg + zb * oBb + zh * oBh) + (size_t)col0 * ldb2;
    float* C = (!c_h16 && Cg) ? (Cg + zb * oCb + zh * oCh) : (float*)0;
    h16* Ch = (c_h16 && Cg) ? ((h16*)Cg + zb * oCb + zh * oCh) : (h16*)0;
    const float* R = resid ? (resid + zb * oCb + zh * oCh) : (const float*)0;
    h16* EA = expAg ? (expAg + (size_t)zb * oCb * 2 + (size_t)zh * oCh * 2) : (h16*)0;
    const int lde = ldc * 2;

    float acc[2][NT][4];
#pragma unroll
    for (int i = 0; i < 2; i++)
#pragma unroll
        for (int j = 0; j < NT; j++)
#pragma unroll
            for (int k = 0; k < 4; k++) acc[i][j][k] = 0.f;

    auto load_stage = [&](int c) {
        int s = c % 3;
        uint32_t sa = sbase + s * STG;
        const char* Ac = A + c * 128;
#pragma unroll
        for (int i = 0; i < (BM * 8) / 256; i++) {
            int cc = tid + i * 256, r = cc >> 3, sg = (cc & 7) * 16;
            cpa16(sa + r * (LT * 2) + sg, Ac + (size_t)r * lda2 + sg);
        }
        uint32_t sb = sa + ASTG;
        const char* Bc = B + c * 128;
#pragma unroll
        for (int i = 0; i < (BN * 8) / 256; i++) {
            int cc = tid + i * 256, r = cc >> 3, sg = (cc & 7) * 16;
            cpa16(sb + r * (LT * 2) + sg, Bc + (size_t)r * ldb2 + sg);
        }
        asm volatile("cp.async.commit_group;\n");
    };

    load_stage(0);
    load_stage(1);

    const int g = lane >> 3, ri = lane & 7;
    for (int c = 0; c < NC; c++) {
        if (c < NC - 1) {
            asm volatile("cp.async.wait_group 1;\n");
        } else {
            asm volatile("cp.async.wait_group 0;\n");
        }
        __syncthreads();
        if (c + 2 < NC) load_stage(c + 2);

        int s = c % 3;
        uint32_t sa = sbase + s * STG;
        uint32_t sb = sa + ASTG;
#pragma unroll
        for (int k16 = 0; k16 < 4; k16++) {
            uint32_t a[2][4];
#pragma unroll
            for (int mt = 0; mt < 2; mt++) {
                int row = wm * 32 + mt * 16 + ri + (g & 1) * 8;
                ldm_x4(a[mt][0], a[mt][1], a[mt][2], a[mt][3],
                       sa + row * (LT * 2) + k16 * 32 + (g >> 1) * 16);
            }
            uint32_t b[NT][2];
#pragma unroll
            for (int np = 0; np < NT / 2; np++) {
                int nrow = wn * (BN / 2) + np * 16 + ri + (g >> 1) * 8;
                ldm_x4(b[2 * np][0], b[2 * np][1], b[2 * np + 1][0], b[2 * np + 1][1],
                       sb + nrow * (LT * 2) + k16 * 32 + (g & 1) * 16);
            }
#pragma unroll
            for (int mt = 0; mt < 2; mt++)
#pragma unroll
                for (int nt = 0; nt < NT; nt++)
                    mma16816(acc[mt][nt], a[mt], b[nt]);
        }
    }
    __syncthreads();

    // epilogue
    float* bins = (float*)sm;  // mainloop smem is dead now
    if (diag) {
        for (int i = tid; i < 512; i += 256) bins[i] = 0.f;
        __syncthreads();
    }
    const int gq = lane >> 2, tq = lane & 3;
#pragma unroll
    for (int mt = 0; mt < 2; mt++) {
#pragma unroll
        for (int nt = 0; nt < NT; nt++) {
            int ccol = col0 + wn * (BN / 2) + nt * 8 + tq * 2;
#pragma unroll
            for (int h = 0; h < 2; h++) {
                int r = row0 + wm * 32 + mt * 16 + gq + h * 8;
                size_t off = (size_t)r * ldc + ccol;
                float v0 = alpha * acc[mt][nt][2 * h];
                float v1 = alpha * acc[mt][nt][2 * h + 1];
                if (bias) { v0 += bias[ccol]; v1 += bias[ccol + 1]; }
                if (R) {
                    float2 p = *(const float2*)&R[off];
                    v0 += p.x; v1 += p.y;
                }
                if (C) {
                    float2 o; o.x = v0; o.y = v1;
                    *(float2*)&C[off] = o;
                }
                if (Ch) {
                    uint32_t pk = (uint32_t)hbits(__float2half(v0)) |
                                  ((uint32_t)hbits(__float2half(v1)) << 16);
                    *(uint32_t*)&Ch[off] = pk;
                }
                if (diag) {
                    atomicAdd(&bins[(r - ccol) & 511], v0);
                    atomicAdd(&bins[(r - ccol - 1) & 511], v1);
                }
                if (EA) {
                    uint32_t* q = (uint32_t*)(EA + (size_t)r * lde + 2 * ccol);
                    q[0] = pack_hilo(v0);
                    q[1] = pack_hilo(v1);
                }
            }
        }
    }
    if (diag) {
        __syncthreads();
        int slot = z * (gridDim.x * gridDim.y) + blockIdx.y * gridDim.x + blockIdx.x;
        float* dd = diag + (size_t)slot * 512;
        for (int i = tid; i < 512; i += 256) dd[i] = bins[i];
    }
}

// ---------------- setup + expansions ----------------
__global__ void setup_misc() {
    int t = threadIdx.x;
    double s = 0.0;
    for (int f = FLEFT; f < 256; ++f)
        s += 2.0 * cos(2.0 * PI_D * (double)f * (double)t / 512.0);
    s += (t & 1) ? -1.0 : 1.0;
    d_g[t] = (float)(s / 512.0);
}
__global__ void expand_G() {
    int l = blockIdx.x, m = threadIdx.x;
    float v = d_g[(l - m) & (NL - 1)];
    *(uint32_t*)&d_Ge[(size_t)l * 1024 + 2 * m] = pack_hilo(v);
}
// PAT 0 = A-pattern (hi,lo); PAT 1 = B-pattern (hi,hi)
template <int PAT>
__global__ void expand_k(const float* __restrict__ src, h16* __restrict__ dst,
                         int K, int src_ld, int Hd, long long oZb, long long oZh, long long dstZ) {
    int z = blockIdx.z, zb = z / Hd, zh = z % Hd;
    const float* s = src + zb * oZb + zh * oZh + (size_t)blockIdx.y * src_ld;
    h16* d = dst + (size_t)z * dstZ + (size_t)blockIdx.y * (2 * K);
    for (int k = blockIdx.x * blockDim.x + threadIdx.x; k < K; k += gridDim.x * blockDim.x) {
        float v = s[k];
        uint32_t pk;
        if (PAT == 0) {
            pk = pack_hilo(v);
        } else {
            h16 h = __float2half(v);
            pk = (uint32_t)hbits(h) | ((uint32_t)hbits(h) << 16);
        }
        *(uint32_t*)&d[2 * k] = pk;
    }
}
// transpose + B-pattern (hi,hi): src [Krows,Ncols] -> dst [Ncols,2*Krows]
__global__ void texpand_b(const float* __restrict__ src, h16* __restrict__ dst,
                          int src_ld, int Krows, int Ncols, int Hd,
                          long long oZb, long long oZh, long long dstZ) {
    __shared__ float t[32][33];
    int z = blockIdx.z, zb = z / Hd, zh = z % Hd;
    const float* s = src + zb * oZb + zh * oZh;
    h16* d = dst + (size_t)z * dstZ;
    int k0 = blockIdx.x * 32, n0 = blockIdx.y * 32;
    int tx = threadIdx.x, ty = threadIdx.y;
#pragma unroll
    for (int i = 0; i < 32; i += 8)
        t[ty + i][tx] = s[(size_t)(k0 + ty + i) * src_ld + n0 + tx];
    __syncthreads();
#pragma unroll
    for (int i = 0; i < 32; i += 8) {
        int n = n0 + ty + i, k = k0 + tx;
        h16 h = __float2half(t[tx][ty + i]);
        uint32_t pk = (uint32_t)hbits(h) | ((uint32_t)hbits(h) << 16);
        *(uint32_t*)&d[(size_t)n * (2 * Krows) + 2 * k] = pk;
    }
}

// ---------------- top-k over per-CTA diag partials ----------------
__global__ void topk_kernel() {
    int b = blockIdx.x, t = threadIdx.x;
    __shared__ float mv[NL], rv[256], selw[NTOPK];
    __shared__ int ri[256], seld[NTOPK];
    for (int d = t; d < NL; d += 256) {
        float s = 0.f;
        for (int sl = 0; sl < 128; sl++) s += d_mvp[((size_t)b * 128 + sl) * 512 + d];
        mv[d] = s * (1.f / 64.f);  // corr = 8*S, mean over 512 channels
    }
    __syncthreads();
    for (int k = 0; k < NTOPK; k++) {
        float best = -1e30f; int bi = NL;
        for (int d = t; d < NL; d += 256) {
            float x = mv[d];
            if (x > best || (x == best && d < bi)) { best = x; bi = d; }
        }
        rv[t] = best; ri[t] = bi;
        __syncthreads();
        for (int off = 128; off; off >>= 1) {
            if (t < off && (rv[t+off] > rv[t] || (rv[t+off] == rv[t] && ri[t+off] < ri[t]))) {
                rv[t] = rv[t+off]; ri[t] = ri[t+off];
            }
            __syncthreads();
        }
        if (t == 0) { selw[k] = rv[0]; seld[k] = ri[0]; mv[ri[0]] = -1e30f; }
        __syncthreads();
    }
    if (t == 0) {
        float m = selw[0], s = 0.f;
        for (int k = 0; k < NTOPK; k++) { float e = expf(selw[k] - m); selw[k] = e; s += e; }
        float inv = 1.f / s;
        for (int k = 0; k < NTOPK; k++) {
            d_w[b * NTOPK + k] = selw[k] * inv;
            d_delay[b * NTOPK + k] = seld[k];
        }
    }
}

__global__ void delay_agg(const float* __restrict__ V, float* __restrict__ ctx) {
    int l = blockIdx.x, b = blockIdx.y, t = threadIdx.x;
    __shared__ float w[NTOPK];
    __shared__ int dl[NTOPK];
    if (t < NTOPK) { w[t] = d_w[b * NTOPK + t]; dl[t] = d_delay[b * NTOPK + t]; }
    __syncthreads();
    const float* Vb = V + (size_t)b * NL * NHID + t;
    float acc = 0.f;
#pragma unroll 2
    for (int k = 0; k < NTOPK; k++)
        acc += w[k] * Vb[(size_t)((l + dl[k]) & (NL - 1)) * NHID];
    ctx[(size_t)b * NL * NHID + (size_t)l * NHID + t] = 0.5f * acc;
}

// softmax(+mask) over fp16 scores, emitting 2-term (hi,lo) expanded probs
__global__ void softmax_se(const h16* __restrict__ S, const float* __restrict__ mask,
                           h16* __restrict__ Se) {
    size_t row = blockIdx.x;
    int b = (int)(row / (NH * NL)), i = (int)(row % NL);
    const h16* s = S + row * NL;
    const float* mr = mask + (size_t)b * NL * NL + (size_t)i * NL;
    h16* se = Se + row * 1024;
    int t = threadIdx.x;
    float v[4], mx = -1e30f;
#pragma unroll
    for (int k = 0; k < 4; k++) {
        v[k] = __half2float(s[t + 128*k]) + mr[t + 128*k];
        mx = fmaxf(mx, v[k]);
    }
    __shared__ float red[32];
#pragma unroll
    for (int o = 16; o; o >>= 1) mx = fmaxf(mx, __shfl_xor_sync(~0u, mx, o));
    if ((t & 31) == 0) red[t >> 5] = mx;
    __syncthreads();
    mx = fmaxf(fmaxf(red[0], red[1]), fmaxf(red[2], red[3]));
    float sum = 0.f;
#pragma unroll
    for (int k = 0; k < 4; k++) { v[k] = expf(v[k] - mx); sum += v[k]; }
#pragma unroll
    for (int o = 16; o; o >>= 1) sum += __shfl_xor_sync(~0u, sum, o);
    __syncthreads();
    if ((t & 31) == 0) red[t >> 5] = sum;
    __syncthreads();
    float inv = 1.f / (red[0] + red[1] + red[2] + red[3]);
#pragma unroll
    for (int k = 0; k < 4; k++) {
        float p = v[k] * inv;
        int col = t + 128 * k;
        *(uint32_t*)&se[2 * col] = pack_hilo(p);
    }
}

__global__ void layernorm(const float* __restrict__ Hb, const float* __restrict__ w,
                          const float* __restrict__ bz, float* __restrict__ out) {
    size_t row = blockIdx.x;
    const float* h = Hb + row * NHID;
    float* o = out + row * NHID;
    int t = threadIdx.x;
    float v[4], s = 0.f;
#pragma unroll
    for (int k = 0; k < 4; k++) { v[k] = h[t + 128*k]; s += v[k]; }
    __shared__ float red[32];
#pragma unroll
    for (int o2 = 16; o2; o2 >>= 1) s += __shfl_xor_sync(~0u, s, o2);
    if ((t & 31) == 0) red[t >> 5] = s;
    __syncthreads();
    float mu = (red[0] + red[1] + red[2] + red[3]) / (float)NHID;
    float s2 = 0.f;
#pragma unroll
    for (int k = 0; k < 4; k++) { float d = v[k] - mu; s2 += d * d; }
#pragma unroll
    for (int o2 = 16; o2; o2 >>= 1) s2 += __shfl_xor_sync(~0u, s2, o2);
    __syncthreads();
    if ((t & 31) == 0) red[t >> 5] = s2;
    __syncthreads();
    float inv = rsqrtf((red[0] + red[1] + red[2] + red[3]) / (float)NHID + 1e-12f);
#pragma unroll
    for (int k = 0; k < 4; k++) {
        int c = t + 128*k;
        o[c] = w[c] * ((v[k] - mu) * inv) + bz[c];
    }
}

// ---------------- launch ----------------
extern "C" void kernel_launch(void* const* d_in, const int* in_sizes, int n_in,
                              void* d_out, int out_size) {
    (void)in_sizes; (void)n_in; (void)out_size;
    const float* x = (const float*)d_in[0];
    const float* mask = (const float*)d_in[1];
    const float* Wq = (const float*)d_in[2];
    const float* Wk = (const float*)d_in[4];
    const float* Wv = (const float*)d_in[6];
    const float* bv = (const float*)d_in[7];
    const float* Wd = (const float*)d_in[8];
    const float* bd = (const float*)d_in[9];
    const float* lnw = (const float*)d_in[10];
    const float* lnb = (const float*)d_in[11];
    float* out = (float*)d_out;

    h16 *pWe, *pWde, *pxe, *pGe, *pxte, *pXge, *pQfe, *pKfe, *pVfte, *pSh, *pSe, *pctxe;
    float *pQKVf, *pV, *pctx, *pHb, *pmvp;
    cudaGetSymbolAddress((void**)&pWe, d_We);
    cudaGetSymbolAddress((void**)&pWde, d_Wde);
    cudaGetSymbolAddress((void**)&pxe, d_xe);
    cudaGetSymbolAddress((void**)&pGe, d_Ge);
    cudaGetSymbolAddress((void**)&pxte, d_xte);
    cudaGetSymbolAddress((void**)&pXge, d_Xge);
    cudaGetSymbolAddress((void**)&pQfe, d_Qfe);
    cudaGetSymbolAddress((void**)&pKfe, d_Kfe);
    cudaGetSymbolAddress((void**)&pVfte, d_Vfte);
    cudaGetSymbolAddress((void**)&pSh, d_S);
    cudaGetSymbolAddress((void**)&pSe, d_Se);
    cudaGetSymbolAddress((void**)&pctxe, d_ctxe);
    cudaGetSymbolAddress((void**)&pQKVf, d_QKVf);
    cudaGetSymbolAddress((void**)&pV, d_V);
    cudaGetSymbolAddress((void**)&pctx, d_ctx);
    cudaGetSymbolAddress((void**)&pHb, d_Hb);
    cudaGetSymbolAddress((void**)&pmvp, d_mvp);

    const int SM128 = 3 * (128 + 128) * 72 * 2;  // 110592 B (3 stages)
    const int SM64  = 3 * (128 + 64) * 72 * 2;   // 82944 B
    cudaFuncSetAttribute(bgemm<128>, cudaFuncAttributeMaxDynamicSharedMemorySize, SM128);
    cudaFuncSetAttribute(bgemm<64>,  cudaFuncAttributeMaxDynamicSharedMemorySize, SM64);

    const long long L1536 = 1536LL * 512;  // per-batch stride of QKVf (f32)
    const long long BLH = 512LL * 512;
    const long long BLL = 512LL * 512;

    setup_misc<<<1, 512>>>();
    expand_G<<<512, 512>>>();
    expand_k<1><<<dim3(2,512,1), 256>>>(Wq, pWe,              512, 512, 1, 0, 0, 0);
    expand_k<1><<<dim3(2,512,1), 256>>>(Wk, pWe + 512*1024,   512, 512, 1, 0, 0, 0);
    expand_k<1><<<dim3(2,512,1), 256>>>(Wv, pWe + 1024*1024,  512, 512, 1, 0, 0, 0);
    expand_k<1><<<dim3(2,512,1), 256>>>(Wd, pWde,             512, 512, 1, 0, 0, 0);
    expand_k<0><<<dim3(2,16384,1), 256>>>(x, pxe,             512, 512, 1, 0, 0, 0);
    // x^T expanded per batch (B operand of the filter GEMM)
    texpand_b<<<dim3(16,16,32), dim3(32,8)>>>(x, pxte, 512, 512, 512, 1,
        BLH, 0, 512LL*1024);

    // 1) filter X: Xge = expand(G @ x[b])  (C store skipped; only expA emitted)
    bgemm<128><<<dim3(4,4,32), 256, SM128>>>(pGe, pxte, nullptr,
        1024, 1024, 512, 1024, 0,0, 512LL*1024,0, BLH,0, 1,
        nullptr, nullptr, pXge, nullptr, 0, 1.f);

    // 2) filtered projections: QKVf = Xg @ [Wq;Wk;Wv]^T  (band kills bias exactly)
    bgemm<128><<<dim3(12,128,1), 256, SM128>>>(pXge, pWe, pQKVf,
        1024, 1024, 1536, 1024, 0,0, 0,0, 0,0, 1,
        nullptr, nullptr, nullptr, nullptr, 0, 1.f);

    // 3) unfiltered V (time branch): V = x @ Wv^T + bv
    bgemm<128><<<dim3(4,128,1), 256, SM128>>>(pxe, pWe + 1024*1024, pV,
        1024, 1024, 512, 1024, 0,0, 0,0, 0,0, 1,
        bv, nullptr, nullptr, nullptr, 0, 1.f);

    // per-head expansions from QKVf
    expand_k<0><<<dim3(1,512,256), 64>>>(pQKVf, pQfe, 64, 1536, 8, L1536, 64, 512LL*128);
    expand_k<1><<<dim3(1,512,256), 64>>>(pQKVf + 512, pKfe, 64, 1536, 8, L1536, 64, 512LL*128);
    texpand_b<<<dim3(16,2,256), dim3(32,8)>>>(pQKVf + 1024, pVfte, 1536, 512, 64, 8,
        L1536, 64, 64LL*1024);

    // 4) scores: S(fp16) = 0.125 * Qf_h @ Kf_h^T, with fused per-CTA diag partials
    bgemm<128><<<dim3(4,4,256), 256, SM128>>>(pQfe, pKfe, (float*)pSh,
        128, 128, 512, 128, 8*512LL*128, 512LL*128, 8*512LL*128, 512LL*128,
        8*BLL, BLL, 8, nullptr, nullptr, nullptr, pmvp, 1, 0.125f);

    // top-k over summed diag partials
    topk_kernel<<<NB, 256>>>();

    // time branch gather
    delay_agg<<<dim3(NL, NB), NHID>>>(pV, pctx);

    // softmax (+mask) -> 2-term expanded probs Se
    softmax_se<<<NB * NH * NL, 128>>>(pSh, mask, pSe);

    // 5) ctxe = expand(0.5*probs@Vf_h + ctx_time)  (resid carries time branch; no C store)
    bgemm<64><<<dim3(1,4,256), 256, SM64>>>(pSe, pVfte, nullptr,
        1024, 1024, 512, 1024, 8*512LL*1024, 512LL*1024, 8*64LL*1024, 64LL*1024,
        BLH, 64, 8, nullptr, pctx, pctxe, nullptr, 0, 0.5f);

    // 6) output projection + bias + residual
    bgemm<128><<<dim3(4,128,1), 256, SM128>>>(pctxe, pWde, pHb,
        1024, 1024, 512, 1024, 0,0, 0,0, 0,0, 1,
        bd, x, nullptr, nullptr, 0, 1.f);

    layernorm<<<NB * NL, 128>>>(pHb, lnw, lnb, out);
}

// round 15
// speedup vs baseline: 1.3285x; 1.1303x over previous
#include <cuda_runtime.h>
#include <cuda_fp16.h>
#include <math.h>
#include <stdint.h>

#define NB 32
#define NL 512
#define NHID 512
#define NH 8
#define NE 64
#define NTOPK 62
#define FLEFT 102
#define PI_D 3.14159265358979323846

typedef __half h16;

// ---------------- static device scratch ----------------
__device__ float d_g[NL];
__device__ h16 d_G1[512 * 512];                    // circulant filter, fp16 1-term
__device__ h16 d_xt1[(size_t)NB * 512 * 512];      // x^T fp16 per batch
__device__ h16 d_x1[(size_t)16384 * 512];          // x fp16
__device__ h16 d_We1[1536 * 512];                  // [Wq;Wk;Wv] fp16 1-term
__device__ h16 d_Wde[512 * 1024];                  // Wd 2-term (hi,hi)
__device__ h16 d_Xg1[(size_t)16384 * 512];         // filtered X fp16 (via c_h16)
__device__ float d_QKVf[(size_t)16384 * 1536];     // Qf|Kf|Vf (f32)
__device__ float d_V[(size_t)16384 * 512];         // unfiltered V (time branch)
__device__ h16 d_Qf1[(size_t)NB * NH * NL * 64];   // per-head Q fp16
__device__ h16 d_Kf1[(size_t)NB * NH * NL * 64];   // per-head K fp16
__device__ h16 d_Vfte[(size_t)NB * NH * NE * 1024];// V^T 2-term (hi,hi)
__device__ h16 d_S[(size_t)NB * NH * NL * NL];     // raw scores, fp16
__device__ h16 d_Se[(size_t)NB * NH * NL * 1024];  // probs 2-term (hi,lo)
__device__ float d_ctx[(size_t)16384 * 512];       // time-branch context
__device__ h16 d_ctxe[(size_t)16384 * 1024];       // ctx expanded 2-term (via expA)
__device__ float d_Hb[(size_t)16384 * 512];
__device__ float d_mvp[(size_t)NB * NH * 16 * NL]; // per-CTA diag partials
__device__ int d_delay[NB * NTOPK];
__device__ float d_w[NB * NTOPK];

// ---------------- helpers ----------------
__device__ __forceinline__ uint32_t smem_u32(const void* p) {
    uint32_t r;
    asm("{ .reg .u64 t; cvta.to.shared.u64 t, %1; cvt.u32.u64 %0, t; }" : "=r"(r) : "l"(p));
    return r;
}
__device__ __forceinline__ void cpa16(uint32_t s, const void* g) {
    asm volatile("cp.async.cg.shared.global [%0], [%1], 16;\n" :: "r"(s), "l"(g));
}
__device__ __forceinline__ void ldm_x4(uint32_t& r0, uint32_t& r1, uint32_t& r2, uint32_t& r3,
                                       uint32_t a) {
    asm volatile("ldmatrix.sync.aligned.m8n8.x4.shared.b16 {%0,%1,%2,%3}, [%4];\n"
                 : "=r"(r0), "=r"(r1), "=r"(r2), "=r"(r3) : "r"(a));
}
__device__ __forceinline__ void mma16816(float* c, const uint32_t* a, const uint32_t* b) {
    asm volatile(
        "mma.sync.aligned.m16n8k16.row.col.f32.f16.f16.f32 "
        "{%0,%1,%2,%3},{%4,%5,%6,%7},{%8,%9},{%0,%1,%2,%3};\n"
        : "+f"(c[0]), "+f"(c[1]), "+f"(c[2]), "+f"(c[3])
        : "r"(a[0]), "r"(a[1]), "r"(a[2]), "r"(a[3]), "r"(b[0]), "r"(b[1]));
}
__device__ __forceinline__ unsigned short hbits(h16 h) {
    return __half_as_ushort(h);
}
__device__ __forceinline__ uint32_t pack_hilo(float v) {
    h16 h = __float2half(v);
    h16 lo = __float2half(v - __half2float(h));
    return (uint32_t)hbits(h) | ((uint32_t)hbits(lo) << 16);
}

// ---------------- fp16 HMMA NT GEMM, 3-stage cp.async pipeline ----------------
// C = alpha*A·B^T (+bias)(+resid); optional expA (2-term hi,lo output),
// optional fp16 C (c_h16), optional per-CTA diagonal partial sums (diag).
template <int BN>
__global__ void __launch_bounds__(256, 2) bgemm(
    const h16* __restrict__ Ag, const h16* __restrict__ Bg, float* __restrict__ Cg,
    int lda, int ldb, int ldc, int Kx,
    long long oAb, long long oAh, long long oBb, long long oBh,
    long long oCb, long long oCh, int Hd,
    const float* __restrict__ bias, const float* __restrict__ resid,
    h16* __restrict__ expAg, float* __restrict__ diag, int c_h16,
    float alpha)
{
    constexpr int BM = 128, LT = 72;
    constexpr int ASTG = BM * LT * 2;
    constexpr int BSTG = BN * LT * 2;
    constexpr int STG = ASTG + BSTG;
    constexpr int NT = BN / 16;
    const int NC = Kx >> 6;

    extern __shared__ h16 sm[];
    const uint32_t sbase = smem_u32(sm);

    const int tid = threadIdx.x;
    const int lane = tid & 31, warp = tid >> 5;
    const int wm = warp >> 1, wn = warp & 1;

    const int z = blockIdx.z, zb = z / Hd, zh = z % Hd;
    const int row0 = blockIdx.y * BM, col0 = blockIdx.x * BN;
    const int lda2 = lda * 2, ldb2 = ldb * 2;
    const char* A = (const char*)(Ag + zb * oAb + zh * oAh) + (size_t)row0 * lda2;
    const char* B = (const char*)(Bg + zb * oBb + zh * oBh) + (size_t)col0 * ldb2;
    float* C = (!c_h16 && Cg) ? (Cg + zb * oCb + zh * oCh) : (float*)0;
    h16* Ch = (c_h16 && Cg) ? ((h16*)Cg + zb * oCb + zh * oCh) : (h16*)0;
    const float* R = resid ? (resid + zb * oCb + zh * oCh) : (const float*)0;
    h16* EA = expAg ? (expAg + (size_t)zb * oCb * 2 + (size_t)zh * oCh * 2) : (h16*)0;
    const int lde = ldc * 2;

    float acc[2][NT][4];
#pragma unroll
    for (int i = 0; i < 2; i++)
#pragma unroll
        for (int j = 0; j < NT; j++)
#pragma unroll
            for (int k = 0; k < 4; k++) acc[i][j][k] = 0.f;

    auto load_stage = [&](int c) {
        int s = c % 3;
        uint32_t sa = sbase + s * STG;
        const char* Ac = A + c * 128;
#pragma unroll
        for (int i = 0; i < (BM * 8) / 256; i++) {
            int cc = tid + i * 256, r = cc >> 3, sg = (cc & 7) * 16;
            cpa16(sa + r * (LT * 2) + sg, Ac + (size_t)r * lda2 + sg);
        }
        uint32_t sb = sa + ASTG;
        const char* Bc = B + c * 128;
#pragma unroll
        for (int i = 0; i < (BN * 8) / 256; i++) {
            int cc = tid + i * 256, r = cc >> 3, sg = (cc & 7) * 16;
            cpa16(sb + r * (LT * 2) + sg, Bc + (size_t)r * ldb2 + sg);
        }
        asm volatile("cp.async.commit_group;\n");
    };

    load_stage(0);
    if (NC > 1) load_stage(1);

    const int g = lane >> 3, ri = lane & 7;
    for (int c = 0; c < NC; c++) {
        if (c < NC - 1) {
            asm volatile("cp.async.wait_group 1;\n");
        } else {
            asm volatile("cp.async.wait_group 0;\n");
        }
        __syncthreads();
        if (c + 2 < NC) load_stage(c + 2);

        int s = c % 3;
        uint32_t sa = sbase + s * STG;
        uint32_t sb = sa + ASTG;
#pragma unroll
        for (int k16 = 0; k16 < 4; k16++) {
            uint32_t a[2][4];
#pragma unroll
            for (int mt = 0; mt < 2; mt++) {
                int row = wm * 32 + mt * 16 + ri + (g & 1) * 8;
                ldm_x4(a[mt][0], a[mt][1], a[mt][2], a[mt][3],
                       sa + row * (LT * 2) + k16 * 32 + (g >> 1) * 16);
            }
            uint32_t b[NT][2];
#pragma unroll
            for (int np = 0; np < NT / 2; np++) {
                int nrow = wn * (BN / 2) + np * 16 + ri + (g >> 1) * 8;
                ldm_x4(b[2 * np][0], b[2 * np][1], b[2 * np + 1][0], b[2 * np + 1][1],
                       sb + nrow * (LT * 2) + k16 * 32 + (g & 1) * 16);
            }
#pragma unroll
            for (int mt = 0; mt < 2; mt++)
#pragma unroll
                for (int nt = 0; nt < NT; nt++)
                    mma16816(acc[mt][nt], a[mt], b[nt]);
        }
    }
    __syncthreads();

    // epilogue
    float* bins = (float*)sm;
    if (diag) {
        for (int i = tid; i < 512; i += 256) bins[i] = 0.f;
        __syncthreads();
    }
    const int gq = lane >> 2, tq = lane & 3;
#pragma unroll
    for (int mt = 0; mt < 2; mt++) {
#pragma unroll
        for (int nt = 0; nt < NT; nt++) {
            int ccol = col0 + wn * (BN / 2) + nt * 8 + tq * 2;
#pragma unroll
            for (int h = 0; h < 2; h++) {
                int r = row0 + wm * 32 + mt * 16 + gq + h * 8;
                size_t off = (size_t)r * ldc + ccol;
                float v0 = alpha * acc[mt][nt][2 * h];
                float v1 = alpha * acc[mt][nt][2 * h + 1];
                if (bias) { v0 += bias[ccol]; v1 += bias[ccol + 1]; }
                if (R) {
                    float2 p = *(const float2*)&R[off];
                    v0 += p.x; v1 += p.y;
                }
                if (C) {
                    float2 o; o.x = v0; o.y = v1;
                    *(float2*)&C[off] = o;
                }
                if (Ch) {
                    uint32_t pk = (uint32_t)hbits(__float2half(v0)) |
                                  ((uint32_t)hbits(__float2half(v1)) << 16);
                    *(uint32_t*)&Ch[off] = pk;
                }
                if (diag) {
                    atomicAdd(&bins[(r - ccol) & 511], v0);
                    atomicAdd(&bins[(r - ccol - 1) & 511], v1);
                }
                if (EA) {
                    uint32_t* q = (uint32_t*)(EA + (size_t)r * lde + 2 * ccol);
                    q[0] = pack_hilo(v0);
                    q[1] = pack_hilo(v1);
                }
            }
        }
    }
    if (diag) {
        __syncthreads();
        int slot = z * (gridDim.x * gridDim.y) + blockIdx.y * gridDim.x + blockIdx.x;
        float* dd = diag + (size_t)slot * 512;
        for (int i = tid; i < 512; i += 256) dd[i] = bins[i];
    }
}

// ---------------- setup + conversions ----------------
__global__ void setup_misc() {
    int t = threadIdx.x;
    double s = 0.0;
    for (int f = FLEFT; f < 256; ++f)
        s += 2.0 * cos(2.0 * PI_D * (double)f * (double)t / 512.0);
    s += (t & 1) ? -1.0 : 1.0;
    d_g[t] = (float)(s / 512.0);
}
__global__ void build_G1() {
    int l = blockIdx.x, m = threadIdx.x;
    d_G1[l * 512 + m] = __float2half(d_g[(l - m) & (NL - 1)]);
}
// fused weight convert: [Wq;Wk;Wv] -> We1 [1536,512] fp16
__global__ void w3cvt(const float* __restrict__ Wq, const float* __restrict__ Wk,
                      const float* __restrict__ Wv) {
    int r = blockIdx.x;
    const float* src = (r < 512) ? (Wq + (size_t)r * 512)
                     : (r < 1024) ? (Wk + (size_t)(r - 512) * 512)
                                  : (Wv + (size_t)(r - 1024) * 512);
    for (int k = threadIdx.x; k < 512; k += blockDim.x)
        d_We1[(size_t)r * 512 + k] = __float2half(src[k]);
}
// generic fp32 -> fp16 copy with z strides
__global__ void cvt16(const float* __restrict__ src, h16* __restrict__ dst,
                      int K, int src_ld, int Hd, long long oZb, long long oZh, long long dstZ) {
    int z = blockIdx.z, zb = z / Hd, zh = z % Hd;
    const float* s = src + zb * oZb + zh * oZh + (size_t)blockIdx.y * src_ld;
    h16* d = dst + (size_t)z * dstZ + (size_t)blockIdx.y * K;
    for (int k = blockIdx.x * blockDim.x + threadIdx.x; k < K; k += gridDim.x * blockDim.x)
        d[k] = __float2half(s[k]);
}
// transpose fp32 -> fp16: src [Krows,Ncols] per batch -> dst [Ncols,Krows]
__global__ void t_cvt16(const float* __restrict__ src, h16* __restrict__ dst,
                        int src_ld, int Krows, int Ncols,
                        long long oZb, long long dstZ) {
    __shared__ float t[32][33];
    int z = blockIdx.z;
    const float* s = src + z * oZb;
    h16* d = dst + (size_t)z * dstZ;
    int k0 = blockIdx.x * 32, n0 = blockIdx.y * 32;
    int tx = threadIdx.x, ty = threadIdx.y;
#pragma unroll
    for (int i = 0; i < 32; i += 8)
        t[ty + i][tx] = s[(size_t)(k0 + ty + i) * src_ld + n0 + tx];
    __syncthreads();
#pragma unroll
    for (int i = 0; i < 32; i += 8) {
        int n = n0 + ty + i, k = k0 + tx;
        d[(size_t)n * Krows + k] = __float2half(t[tx][ty + i]);
    }
}
// Wd 2-term expand (B-pattern hi,hi): [512,512] -> [512,1024]
__global__ void expand_wd(const float* __restrict__ Wd) {
    int r = blockIdx.x;
    for (int k = threadIdx.x; k < 512; k += blockDim.x) {
        h16 h = __float2half(Wd[(size_t)r * 512 + k]);
        uint32_t pk = (uint32_t)hbits(h) | ((uint32_t)hbits(h) << 16);
        *(uint32_t*)&d_Wde[(size_t)r * 1024 + 2 * k] = pk;
    }
}
// transpose + 2-term (hi,hi): src [Krows,Ncols] -> dst [Ncols,2*Krows]
__global__ void texpand_b(const float* __restrict__ src, h16* __restrict__ dst,
                          int src_ld, int Krows, int Ncols, int Hd,
                          long long oZb, long long oZh, long long dstZ) {
    __shared__ float t[32][33];
    int z = blockIdx.z, zb = z / Hd, zh = z % Hd;
    const float* s = src + zb * oZb + zh * oZh;
    h16* d = dst + (size_t)z * dstZ;
    int k0 = blockIdx.x * 32, n0 = blockIdx.y * 32;
    int tx = threadIdx.x, ty = threadIdx.y;
#pragma unroll
    for (int i = 0; i < 32; i += 8)
        t[ty + i][tx] = s[(size_t)(k0 + ty + i) * src_ld + n0 + tx];
    __syncthreads();
#pragma unroll
    for (int i = 0; i < 32; i += 8) {
        int n = n0 + ty + i, k = k0 + tx;
        h16 h = __float2half(t[tx][ty + i]);
        uint32_t pk = (uint32_t)hbits(h) | ((uint32_t)hbits(h) << 16);
        *(uint32_t*)&d[(size_t)n * (2 * Krows) + 2 * k] = pk;
    }
}

// ---------------- top-k over per-CTA diag partials ----------------
__global__ void topk_kernel() {
    int b = blockIdx.x, t = threadIdx.x;
    __shared__ float mv[NL], rv[256], selw[NTOPK];
    __shared__ int ri[256], seld[NTOPK];
    for (int d = t; d < NL; d += 256) {
        float s = 0.f;
        for (int sl = 0; sl < 128; sl++) s += d_mvp[((size_t)b * 128 + sl) * 512 + d];
        mv[d] = s * (1.f / 64.f);  // corr = 8*S, mean over 512 channels
    }
    __syncthreads();
    for (int k = 0; k < NTOPK; k++) {
        float best = -1e30f; int bi = NL;
        for (int d = t; d < NL; d += 256) {
            float x = mv[d];
            if (x > best || (x == best && d < bi)) { best = x; bi = d; }
        }
        rv[t] = best; ri[t] = bi;
        __syncthreads();
        for (int off = 128; off; off >>= 1) {
            if (t < off && (rv[t+off] > rv[t] || (rv[t+off] == rv[t] && ri[t+off] < ri[t]))) {
                rv[t] = rv[t+off]; ri[t] = ri[t+off];
            }
            __syncthreads();
        }
        if (t == 0) { selw[k] = rv[0]; seld[k] = ri[0]; mv[ri[0]] = -1e30f; }
        __syncthreads();
    }
    if (t == 0) {
        float m = selw[0], s = 0.f;
        for (int k = 0; k < NTOPK; k++) { float e = expf(selw[k] - m); selw[k] = e; s += e; }
        float inv = 1.f / s;
        for (int k = 0; k < NTOPK; k++) {
            d_w[b * NTOPK + k] = selw[k] * inv;
            d_delay[b * NTOPK + k] = seld[k];
        }
    }
}

__global__ void delay_agg(const float* __restrict__ V, float* __restrict__ ctx) {
    int l = blockIdx.x, b = blockIdx.y, t = threadIdx.x;
    __shared__ float w[NTOPK];
    __shared__ int dl[NTOPK];
    if (t < NTOPK) { w[t] = d_w[b * NTOPK + t]; dl[t] = d_delay[b * NTOPK + t]; }
    __syncthreads();
    const float* Vb = V + (size_t)b * NL * NHID + t;
    float acc = 0.f;
#pragma unroll 2
    for (int k = 0; k < NTOPK; k++)
        acc += w[k] * Vb[(size_t)((l + dl[k]) & (NL - 1)) * NHID];
    ctx[(size_t)b * NL * NHID + (size_t)l * NHID + t] = 0.5f * acc;
}

// softmax(+mask) over fp16 scores, emitting 2-term (hi,lo) expanded probs
__global__ void softmax_se(const h16* __restrict__ S, const float* __restrict__ mask,
                           h16* __restrict__ Se) {
    size_t row = blockIdx.x;
    int b = (int)(row / (NH * NL)), i = (int)(row % NL);
    const h16* s = S + row * NL;
    const float* mr = mask + (size_t)b * NL * NL + (size_t)i * NL;
    h16* se = Se + row * 1024;
    int t = threadIdx.x;
    float v[4], mx = -1e30f;
#pragma unroll
    for (int k = 0; k < 4; k++) {
        v[k] = __half2float(s[t + 128*k]) + mr[t + 128*k];
        mx = fmaxf(mx, v[k]);
    }
    __shared__ float red[32];
#pragma unroll
    for (int o = 16; o; o >>= 1) mx = fmaxf(mx, __shfl_xor_sync(~0u, mx, o));
    if ((t & 31) == 0) red[t >> 5] = mx;
    __syncthreads();
    mx = fmaxf(fmaxf(red[0], red[1]), fmaxf(red[2], red[3]));
    float sum = 0.f;
#pragma unroll
    for (int k = 0; k < 4; k++) { v[k] = expf(v[k] - mx); sum += v[k]; }
#pragma unroll
    for (int o = 16; o; o >>= 1) sum += __shfl_xor_sync(~0u, sum, o);
    __syncthreads();
    if ((t & 31) == 0) red[t >> 5] = sum;
    __syncthreads();
    float inv = 1.f / (red[0] + red[1] + red[2] + red[3]);
#pragma unroll
    for (int k = 0; k < 4; k++) {
        float p = v[k] * inv;
        int col = t + 128 * k;
        *(uint32_t*)&se[2 * col] = pack_hilo(p);
    }
}

__global__ void layernorm(const float* __restrict__ Hb, const float* __restrict__ w,
                          const float* __restrict__ bz, float* __restrict__ out) {
    size_t row = blockIdx.x;
    const float* h = Hb + row * NHID;
    float* o = out + row * NHID;
    int t = threadIdx.x;
    float v[4], s = 0.f;
#pragma unroll
    for (int k = 0; k < 4; k++) { v[k] = h[t + 128*k]; s += v[k]; }
    __shared__ float red[32];
#pragma unroll
    for (int o2 = 16; o2; o2 >>= 1) s += __shfl_xor_sync(~0u, s, o2);
    if ((t & 31) == 0) red[t >> 5] = s;
    __syncthreads();
    float mu = (red[0] + red[1] + red[2] + red[3]) / (float)NHID;
    float s2 = 0.f;
#pragma unroll
    for (int k = 0; k < 4; k++) { float d = v[k] - mu; s2 += d * d; }
#pragma unroll
    for (int o2 = 16; o2; o2 >>= 1) s2 += __shfl_xor_sync(~0u, s2, o2);
    __syncthreads();
    if ((t & 31) == 0) red[t >> 5] = s2;
    __syncthreads();
    float inv = rsqrtf((red[0] + red[1] + red[2] + red[3]) / (float)NHID + 1e-12f);
#pragma unroll
    for (int k = 0; k < 4; k++) {
        int c = t + 128*k;
        o[c] = w[c] * ((v[k] - mu) * inv) + bz[c];
    }
}

// ---------------- launch ----------------
extern "C" void kernel_launch(void* const* d_in, const int* in_sizes, int n_in,
                              void* d_out, int out_size) {
    (void)in_sizes; (void)n_in; (void)out_size;
    const float* x = (const float*)d_in[0];
    const float* mask = (const float*)d_in[1];
    const float* Wq = (const float*)d_in[2];
    const float* Wk = (const float*)d_in[4];
    const float* Wv = (const float*)d_in[6];
    const float* bv = (const float*)d_in[7];
    const float* Wd = (const float*)d_in[8];
    const float* bd = (const float*)d_in[9];
    const float* lnw = (const float*)d_in[10];
    const float* lnb = (const float*)d_in[11];
    float* out = (float*)d_out;

    h16 *pG1, *pxt1, *px1, *pWe1, *pWde, *pXg1, *pQf1, *pKf1, *pVfte, *pSh, *pSe, *pctxe;
    float *pQKVf, *pV, *pctx, *pHb, *pmvp;
    cudaGetSymbolAddress((void**)&pG1, d_G1);
    cudaGetSymbolAddress((void**)&pxt1, d_xt1);
    cudaGetSymbolAddress((void**)&px1, d_x1);
    cudaGetSymbolAddress((void**)&pWe1, d_We1);
    cudaGetSymbolAddress((void**)&pWde, d_Wde);
    cudaGetSymbolAddress((void**)&pXg1, d_Xg1);
    cudaGetSymbolAddress((void**)&pQf1, d_Qf1);
    cudaGetSymbolAddress((void**)&pKf1, d_Kf1);
    cudaGetSymbolAddress((void**)&pVfte, d_Vfte);
    cudaGetSymbolAddress((void**)&pSh, d_S);
    cudaGetSymbolAddress((void**)&pSe, d_Se);
    cudaGetSymbolAddress((void**)&pctxe, d_ctxe);
    cudaGetSymbolAddress((void**)&pQKVf, d_QKVf);
    cudaGetSymbolAddress((void**)&pV, d_V);
    cudaGetSymbolAddress((void**)&pctx, d_ctx);
    cudaGetSymbolAddress((void**)&pHb, d_Hb);
    cudaGetSymbolAddress((void**)&pmvp, d_mvp);

    const int SM128 = 3 * (128 + 128) * 72 * 2;  // 110592 B
    const int SM64  = 3 * (128 + 64) * 72 * 2;   // 82944 B
    cudaFuncSetAttribute(bgemm<128>, cudaFuncAttributeMaxDynamicSharedMemorySize, SM128);
    cudaFuncSetAttribute(bgemm<64>,  cudaFuncAttributeMaxDynamicSharedMemorySize, SM64);

    const long long L1536 = 1536LL * 512;  // per-batch stride of QKVf (f32)
    const long long BLH = 512LL * 512;
    const long long BLL = 512LL * 512;

    // launches 1-5 (so launch #6 = projection GEMM, captured by ncu -s 5 -c 1)
    setup_misc<<<1, 512>>>();                                     // 1
    build_G1<<<512, 512>>>();                                     // 2
    t_cvt16<<<dim3(16,16,32), dim3(32,8)>>>(x, pxt1, 512, 512, 512, BLH, BLH); // 3
    w3cvt<<<1536, 256>>>(Wq, Wk, Wv);                             // 4
    // 5) filter: Xg1(fp16) = G1 @ x[b]  (c_h16 output)
    bgemm<128><<<dim3(4,4,32), 256, SM128>>>(pG1, pxt1, (float*)pXg1,
        512, 512, 512, 512, 0,0, BLH,0, BLH,0, 1,
        nullptr, nullptr, nullptr, nullptr, 1, 1.f);
    // 6) projections: QKVf = Xg1 @ We1^T   <-- profiled launch
    bgemm<128><<<dim3(12,128,1), 256, SM128>>>(pXg1, pWe1, pQKVf,
        512, 512, 1536, 512, 0,0, 0,0, 0,0, 1,
        nullptr, nullptr, nullptr, nullptr, 0, 1.f);

    cvt16<<<dim3(2,16384,1), 256>>>(x, px1, 512, 512, 1, 0, 0, 0);
    expand_wd<<<512, 256>>>(Wd);

    // unfiltered V (time branch): V = x1 @ Wv1^T + bv
    bgemm<128><<<dim3(4,128,1), 256, SM128>>>(px1, pWe1 + 1024*512, pV,
        512, 512, 512, 512, 0,0, 0,0, 0,0, 1,
        bv, nullptr, nullptr, nullptr, 0, 1.f);

    // per-head conversions from QKVf
    cvt16<<<dim3(1,512,256), 64>>>(pQKVf, pQf1, 64, 1536, 8, L1536, 64, 512LL*64);
    cvt16<<<dim3(1,512,256), 64>>>(pQKVf + 512, pKf1, 64, 1536, 8, L1536, 64, 512LL*64);
    texpand_b<<<dim3(16,2,256), dim3(32,8)>>>(pQKVf + 1024, pVfte, 1536, 512, 64, 8,
        L1536, 64, 64LL*1024);

    // scores: S(fp16) = 0.125 * Qf1_h @ Kf1_h^T (Kx=64, single chunk) + diag partials
    bgemm<128><<<dim3(4,4,256), 256, SM128>>>(pQf1, pKf1, (float*)pSh,
        64, 64, 512, 64, 8*512LL*64, 512LL*64, 8*512LL*64, 512LL*64,
        8*BLL, BLL, 8, nullptr, nullptr, nullptr, pmvp, 1, 0.125f);

    topk_kernel<<<NB, 256>>>();
    delay_agg<<<dim3(NL, NB), NHID>>>(pV, pctx);
    softmax_se<<<NB * NH * NL, 128>>>(pSh, mask, pSe);

    // ctxe = expand(0.5*probs@Vf_h + ctx_time)  (2-term Se x 2-term Vfte)
    bgemm<64><<<dim3(1,4,256), 256, SM64>>>(pSe, pVfte, nullptr,
        1024, 1024, 512, 1024, 8*512LL*1024, 512LL*1024, 8*64LL*1024, 64LL*1024,
        BLH, 64, 8, nullptr, pctx, pctxe, nullptr, 0, 0.5f);

    // output projection + bias + residual (2-term ctxe x 2-term Wde)
    bgemm<128><<<dim3(4,128,1), 256, SM128>>>(pctxe, pWde, pHb,
        1024, 1024, 512, 1024, 0,0, 0,0, 0,0, 1,
        bd, x, nullptr, nullptr, 0, 1.f);

    layernorm<<<NB * NL, 128>>>(pHb, lnw, lnb, out);
}